// round 2
// baseline (speedup 1.0000x reference)
#include <cuda_runtime.h>
#include <cuda_bf16.h>
#include <cfloat>
#include <math.h>

// Problem constants
#define BB   16
#define SS   8192
#define AD   512      // attention dim
#define KD   512      // key dim
#define MTOT (BB * SS)   // 131072 rows in the big GEMM

#define Bb_M 128
#define Bb_N 128
#define Bb_K 16

// Scratch (device globals; no allocation allowed)
__device__ float g_qp[BB * AD];                  // q = query @ Wq          (32 KB)
__device__ float g_epart[4 * MTOT];              // per-N-tile partial e    (2 MB)
__device__ float g_cpart[64 * BB * KD];          // per-S-chunk partial c   (2 MB)

// ---------------------------------------------------------------------------
// Kernel 1: q projection  q[b][a] = sum_j query[b][j] * Wq[j][a]
// ---------------------------------------------------------------------------
__global__ void qproj_kernel(const float* __restrict__ query,
                             const float* __restrict__ Wq) {
    __shared__ float qs[AD];
    const int b = blockIdx.x;
    const int a = threadIdx.x;      // 512 threads
    qs[a] = query[b * AD + a];
    __syncthreads();
    float acc = 0.f;
    #pragma unroll 8
    for (int j = 0; j < AD; j++) acc += qs[j] * Wq[j * AD + a];
    g_qp[b * AD + a] = acc;
}

// ---------------------------------------------------------------------------
// Kernel 2: big GEMM (keys[131072,512] @ Wk[512,512]) + fused tanh/v epilogue.
// Each 128x128 tile reduces its columns into a partial e row-sum; the 4
// N-tiles write disjoint partial buffers (deterministic, no atomics).
// ---------------------------------------------------------------------------
__global__ __launch_bounds__(256, 2)
void score_gemm(const float* __restrict__ keys,
                const float* __restrict__ Wk,
                const float* __restrict__ vvec) {
    __shared__ float As[2][Bb_K][Bb_M + 4];
    __shared__ float Bs[2][Bb_K][Bb_N + 4];

    const int tid = threadIdx.x;
    const int nt  = blockIdx.x;      // 0..3
    const int mt  = blockIdx.y;      // 0..1023
    const int tx  = tid & 15;
    const int ty  = tid >> 4;

    const float* Ab  = keys + (size_t)mt * Bb_M * KD;
    const float* Bbp = Wk + nt * Bb_N;

    const int arow = tid >> 2;        // 0..63
    const int ac4  = (tid & 3) * 4;   // 0,4,8,12
    const int brow = tid >> 5;        // 0..7
    const int bc4  = (tid & 31) * 4;

    float acc[8][8];
    #pragma unroll
    for (int i = 0; i < 8; i++)
        #pragma unroll
        for (int j = 0; j < 8; j++) acc[i][j] = 0.f;

    // prologue: stage 0
    #pragma unroll
    for (int p = 0; p < 2; p++) {
        float4 av = *reinterpret_cast<const float4*>(Ab + (size_t)(arow + p * 64) * KD + ac4);
        As[0][ac4 + 0][arow + p * 64] = av.x;
        As[0][ac4 + 1][arow + p * 64] = av.y;
        As[0][ac4 + 2][arow + p * 64] = av.z;
        As[0][ac4 + 3][arow + p * 64] = av.w;
    }
    #pragma unroll
    for (int p = 0; p < 2; p++) {
        float4 bv = *reinterpret_cast<const float4*>(Bbp + (size_t)(brow + p * 8) * AD + bc4);
        *reinterpret_cast<float4*>(&Bs[0][brow + p * 8][bc4]) = bv;
    }
    __syncthreads();

    const int NSTAGES = KD / Bb_K;   // 32
    float4 pa0, pa1, pb0, pb1;

    for (int ks = 0; ks < NSTAGES; ks++) {
        const int buf = ks & 1;
        if (ks + 1 < NSTAGES) {
            const int k0 = (ks + 1) * Bb_K;
            pa0 = *reinterpret_cast<const float4*>(Ab + (size_t)arow * KD + k0 + ac4);
            pa1 = *reinterpret_cast<const float4*>(Ab + (size_t)(arow + 64) * KD + k0 + ac4);
            pb0 = *reinterpret_cast<const float4*>(Bbp + (size_t)(k0 + brow) * AD + bc4);
            pb1 = *reinterpret_cast<const float4*>(Bbp + (size_t)(k0 + brow + 8) * AD + bc4);
        }
        #pragma unroll
        for (int kk = 0; kk < Bb_K; kk++) {
            float4 a0 = *reinterpret_cast<const float4*>(&As[buf][kk][ty * 8]);
            float4 a1 = *reinterpret_cast<const float4*>(&As[buf][kk][ty * 8 + 4]);
            float4 b0 = *reinterpret_cast<const float4*>(&Bs[buf][kk][tx * 8]);
            float4 b1 = *reinterpret_cast<const float4*>(&Bs[buf][kk][tx * 8 + 4]);
            float af[8] = {a0.x, a0.y, a0.z, a0.w, a1.x, a1.y, a1.z, a1.w};
            float bf[8] = {b0.x, b0.y, b0.z, b0.w, b1.x, b1.y, b1.z, b1.w};
            #pragma unroll
            for (int i = 0; i < 8; i++)
                #pragma unroll
                for (int j = 0; j < 8; j++)
                    acc[i][j] += af[i] * bf[j];
        }
        if (ks + 1 < NSTAGES) {
            const int nb = buf ^ 1;
            As[nb][ac4 + 0][arow]      = pa0.x;
            As[nb][ac4 + 1][arow]      = pa0.y;
            As[nb][ac4 + 2][arow]      = pa0.z;
            As[nb][ac4 + 3][arow]      = pa0.w;
            As[nb][ac4 + 0][arow + 64] = pa1.x;
            As[nb][ac4 + 1][arow + 64] = pa1.y;
            As[nb][ac4 + 2][arow + 64] = pa1.z;
            As[nb][ac4 + 3][arow + 64] = pa1.w;
            *reinterpret_cast<float4*>(&Bs[nb][brow][bc4])     = pb0;
            *reinterpret_cast<float4*>(&Bs[nb][brow + 8][bc4]) = pb1;
        }
        __syncthreads();
    }

    // fused epilogue: es[row] = sum_j tanh(acc + qp[col]) * v[col]
    const int m0 = mt * Bb_M;
    const int b  = m0 >> 13;          // /8192, tile never straddles a batch
    const int n0 = nt * Bb_N;

    float qv[8], vv[8];
    #pragma unroll
    for (int j = 0; j < 8; j++) {
        const int col = n0 + tx * 8 + j;
        qv[j] = g_qp[b * AD + col];
        vv[j] = vvec[col];
    }

    float es[8];
    #pragma unroll
    for (int i = 0; i < 8; i++) {
        float s = 0.f;
        #pragma unroll
        for (int j = 0; j < 8; j++)
            s += tanhf(acc[i][j] + qv[j]) * vv[j];
        es[i] = s;
    }

    // reduce across the 16 tx lanes (half-warp groups: lane = (ty&1)*16 + tx)
    #pragma unroll
    for (int off = 8; off > 0; off >>= 1) {
        #pragma unroll
        for (int i = 0; i < 8; i++)
            es[i] += __shfl_xor_sync(0xffffffffu, es[i], off);
    }
    if (tx == 0) {
        #pragma unroll
        for (int i = 0; i < 8; i++)
            g_epart[nt * MTOT + m0 + ty * 8 + i] = es[i];
    }
}

// ---------------------------------------------------------------------------
// Kernel 3: masked softmax over S per batch; writes a into out[16*512 + ...]
// ---------------------------------------------------------------------------
__global__ __launch_bounds__(1024)
void softmax_kernel(const int* __restrict__ mask, float* __restrict__ out) {
    const int b = blockIdx.x;
    const int t = threadIdx.x;
    const int lane = t & 31;
    const int wid  = t >> 5;
    __shared__ float sred[32];

    float sc[8];
    #pragma unroll
    for (int r = 0; r < 8; r++) {
        const int s = t + r * 1024;
        float e = g_epart[0 * MTOT + b * SS + s]
                + g_epart[1 * MTOT + b * SS + s]
                + g_epart[2 * MTOT + b * SS + s]
                + g_epart[3 * MTOT + b * SS + s];
        if (mask[b * SS + s] == 0) e = -FLT_MAX;
        sc[r] = e;
    }

    // block max
    float m = sc[0];
    #pragma unroll
    for (int r = 1; r < 8; r++) m = fmaxf(m, sc[r]);
    #pragma unroll
    for (int off = 16; off > 0; off >>= 1)
        m = fmaxf(m, __shfl_xor_sync(0xffffffffu, m, off));
    if (lane == 0) sred[wid] = m;
    __syncthreads();
    if (t < 32) {
        float x = sred[t];
        #pragma unroll
        for (int off = 16; off > 0; off >>= 1)
            x = fmaxf(x, __shfl_xor_sync(0xffffffffu, x, off));
        if (t == 0) sred[0] = x;
    }
    __syncthreads();
    m = sred[0];
    __syncthreads();   // everyone has read sred[0] before it is reused

    // exp + block sum
    float ex[8];
    float sum = 0.f;
    #pragma unroll
    for (int r = 0; r < 8; r++) {
        ex[r] = expf(sc[r] - m);     // masked -> exp(-huge) == 0 exactly
        sum += ex[r];
    }
    #pragma unroll
    for (int off = 16; off > 0; off >>= 1)
        sum += __shfl_xor_sync(0xffffffffu, sum, off);
    if (lane == 0) sred[wid] = sum;
    __syncthreads();
    if (t < 32) {
        float x = sred[t];
        #pragma unroll
        for (int off = 16; off > 0; off >>= 1)
            x += __shfl_xor_sync(0xffffffffu, x, off);
        if (t == 0) sred[0] = x;
    }
    __syncthreads();
    const float inv = 1.f / sred[0];

    #pragma unroll
    for (int r = 0; r < 8; r++)
        out[BB * KD + b * SS + t + r * 1024] = ex[r] * inv;
}

// ---------------------------------------------------------------------------
// Kernel 4: context partials  cpart[chunk][b][k] = sum_{s in chunk} a * keys
// ---------------------------------------------------------------------------
__global__ __launch_bounds__(256)
void ctx_part_kernel(const float* __restrict__ keys,
                     const float* __restrict__ aout) {
    const int scn = blockIdx.x;   // 0..63 (128-row S chunks)
    const int b   = blockIdx.y;
    const int t   = threadIdx.x;  // 256
    __shared__ float as[128];
    if (t < 128) as[t] = aout[b * SS + scn * 128 + t];
    __syncthreads();

    const float* kb = keys + ((size_t)b * SS + (size_t)scn * 128) * KD;
    float s0 = 0.f, s1 = 0.f;
    for (int s = 0; s < 128; s++) {
        const float av = as[s];
        if (av != 0.f) {              // masked rows contribute exactly 0
            s0 += av * kb[(size_t)s * KD + t];
            s1 += av * kb[(size_t)s * KD + t + 256];
        }
    }
    g_cpart[(scn * BB + b) * KD + t]       = s0;
    g_cpart[(scn * BB + b) * KD + t + 256] = s1;
}

// ---------------------------------------------------------------------------
// Kernel 5: reduce context partials -> out[b*512 + k]
// ---------------------------------------------------------------------------
__global__ __launch_bounds__(512)
void ctx_reduce_kernel(float* __restrict__ out) {
    const int b = blockIdx.x;
    const int t = threadIdx.x;   // 512
    float s = 0.f;
    #pragma unroll 8
    for (int scn = 0; scn < 64; scn++)
        s += g_cpart[(scn * BB + b) * KD + t];
    out[b * KD + t] = s;
}

// ---------------------------------------------------------------------------
extern "C" void kernel_launch(void* const* d_in, const int* in_sizes, int n_in,
                              void* d_out, int out_size) {
    const float* query = (const float*)d_in[0];  // [16, 512]
    const float* keys  = (const float*)d_in[1];  // [16, 8192, 512]
    const int*   mask  = (const int*)  d_in[2];  // [16, 8192]
    const float* Wq    = (const float*)d_in[3];  // [512, 512]
    const float* Wk    = (const float*)d_in[4];  // [512, 512]
    const float* v     = (const float*)d_in[5];  // [512]
    float* out = (float*)d_out;                  // [c: 16*512 | a: 16*8192]

    qproj_kernel<<<BB, AD>>>(query, Wq);
    score_gemm<<<dim3(4, MTOT / Bb_M), 256>>>(keys, Wk, v);
    softmax_kernel<<<BB, 1024>>>(mask, out);
    ctx_part_kernel<<<dim3(64, BB), 256>>>(keys, out + BB * KD);
    ctx_reduce_kernel<<<BB, 512>>>(out);
}

// round 4
// speedup vs baseline: 3.2957x; 3.2957x over previous
#include <cuda_runtime.h>
#include <cuda_bf16.h>
#include <cfloat>
#include <math.h>
#include <cstdint>

// Problem constants
#define BB   16
#define SS   8192
#define AD   512
#define KD   512
#define MTOT (BB * SS)

// ---------------------------------------------------------------------------
// Scratch globals
// ---------------------------------------------------------------------------
__device__ float         g_qp[BB * AD];
__device__ float         g_epart[4 * MTOT];
__device__ float         g_cpart[64 * BB * KD];
__device__ __nv_bfloat16 g_Bt_hi[AD * KD];   // n-major: [n][k] = hi(Wk[k][n])
__device__ __nv_bfloat16 g_Bt_lo[AD * KD];

// ---------------------------------------------------------------------------
// PTX helpers
// ---------------------------------------------------------------------------
__device__ __forceinline__ uint32_t smem_u32(const void* p) {
    uint32_t a;
    asm("{ .reg .u64 t; cvta.to.shared.u64 t, %1; cvt.u32.u64 %0, t; }" : "=r"(a) : "l"(p));
    return a;
}
__device__ __forceinline__ float tanh_fast(float x) {
    float y;
    asm("tanh.approx.f32 %0, %1;" : "=f"(y) : "f"(x));
    return y;
}
__device__ __forceinline__ void ldsm_x4(uint32_t* r, uint32_t addr) {
    asm volatile("ldmatrix.sync.aligned.m8n8.x4.shared.b16 {%0,%1,%2,%3}, [%4];"
                 : "=r"(r[0]), "=r"(r[1]), "=r"(r[2]), "=r"(r[3]) : "r"(addr));
}
__device__ __forceinline__ void mma16816(float* d, const uint32_t* a, const uint32_t* b) {
    asm volatile(
        "mma.sync.aligned.m16n8k16.row.col.f32.bf16.bf16.f32 "
        "{%0,%1,%2,%3}, {%4,%5,%6,%7}, {%8,%9}, {%0,%1,%2,%3};"
        : "+f"(d[0]), "+f"(d[1]), "+f"(d[2]), "+f"(d[3])
        : "r"(a[0]), "r"(a[1]), "r"(a[2]), "r"(a[3]), "r"(b[0]), "r"(b[1]));
}

// ---------------------------------------------------------------------------
// Kernel 0: prep Wk -> n-major bf16 hi/lo   g_Bt[n*512+k]
// ---------------------------------------------------------------------------
__global__ void prep_wk_kernel(const float* __restrict__ Wk) {
    const int k = blockIdx.x;     // input dim
    const int n = threadIdx.x;    // attn dim
    const float x = Wk[k * AD + n];
    const __nv_bfloat16 hi = __float2bfloat16(x);
    const __nv_bfloat16 lo = __float2bfloat16(x - __bfloat162float(hi));
    g_Bt_hi[n * KD + k] = hi;
    g_Bt_lo[n * KD + k] = lo;
}

// ---------------------------------------------------------------------------
// Kernel 1: q projection
// ---------------------------------------------------------------------------
__global__ void qproj_kernel(const float* __restrict__ query,
                             const float* __restrict__ Wq) {
    __shared__ float qs[AD];
    const int b = blockIdx.x;
    const int a = threadIdx.x;
    qs[a] = query[b * AD + a];
    __syncthreads();
    float acc = 0.f;
    #pragma unroll 8
    for (int j = 0; j < AD; j++) acc += qs[j] * Wq[j * AD + a];
    g_qp[b * AD + a] = acc;
}

// ---------------------------------------------------------------------------
// Kernel 2: mma.sync bf16 3-term GEMM + fused tanh/v epilogue
//   grid (4 nt, 1024 mt), 256 threads = 8 warps (2 M x 4 N), warp 64x32
//   K chunk 32, single SMEM buffer + register prefetch
// ---------------------------------------------------------------------------
#define PADK 40   // 32 + 8 bf16 pad -> 80B row stride, ldmatrix conflict-free

__global__ __launch_bounds__(256)
void score_gemm_mma(const float* __restrict__ keys,
                    const float* __restrict__ vvec) {
    __shared__ __nv_bfloat16 As_hi[128 * PADK];
    __shared__ __nv_bfloat16 As_lo[128 * PADK];
    __shared__ __nv_bfloat16 Bs_hi[128 * PADK];
    __shared__ __nv_bfloat16 Bs_lo[128 * PADK];
    __shared__ float e_red[4][128];

    const int tid = threadIdx.x;
    const int wid = tid >> 5;
    const int lid = tid & 31;
    const int wm  = wid & 1;        // warp M (2)
    const int wn  = wid >> 1;       // warp N (4)
    const int nt  = blockIdx.x;     // 0..3
    const int mt  = blockIdx.y;     // 0..1023
    const int m0  = mt * 128;
    const int b   = mt >> 6;

    const uint32_t sAh = smem_u32(As_hi);
    const uint32_t sAl = smem_u32(As_lo);
    const uint32_t sBh = smem_u32(Bs_hi);
    const uint32_t sBl = smem_u32(Bs_lo);

    // loader mapping: 512 granules of 8 elems; 2 per thread (g = tid, tid+256)
    const int g0row = tid >> 2,         g0c = (tid & 3) * 8;
    const int g1row = (tid + 256) >> 2, g1c = ((tid + 256) & 3) * 8;

    const float* keysA = keys + (size_t)m0 * KD;
    const __nv_bfloat16* BtH = g_Bt_hi + (size_t)(nt * 128) * KD;
    const __nv_bfloat16* BtL = g_Bt_lo + (size_t)(nt * 128) * KD;

    float acc[4][4][4];
    #pragma unroll
    for (int i = 0; i < 4; i++)
        #pragma unroll
        for (int j = 0; j < 4; j++)
            #pragma unroll
            for (int e = 0; e < 4; e++) acc[i][j][e] = 0.f;

    float4 pa[4];
    uint4  pbh[2], pbl[2];

    // prefetch chunk 0
    {
        const float* a0 = keysA + (size_t)g0row * KD + g0c;
        const float* a1 = keysA + (size_t)g1row * KD + g1c;
        pa[0] = *(const float4*)(a0);     pa[1] = *(const float4*)(a0 + 4);
        pa[2] = *(const float4*)(a1);     pa[3] = *(const float4*)(a1 + 4);
        pbh[0] = *(const uint4*)(BtH + (size_t)g0row * KD + g0c);
        pbh[1] = *(const uint4*)(BtH + (size_t)g1row * KD + g1c);
        pbl[0] = *(const uint4*)(BtL + (size_t)g0row * KD + g0c);
        pbl[1] = *(const uint4*)(BtL + (size_t)g1row * KD + g1c);
    }

    for (int kc = 0; kc < 16; kc++) {
        // ---- store prefetched chunk into SMEM (A converted to hi/lo) ----
        #pragma unroll
        for (int h = 0; h < 2; h++) {
            const int row = h ? g1row : g0row;
            const int c8  = h ? g1c  : g0c;
            const float* xs = (const float*)&pa[h * 2];
            uint4 hv, lv;
            __nv_bfloat162* hp = (__nv_bfloat162*)&hv;
            __nv_bfloat162* lp = (__nv_bfloat162*)&lv;
            #pragma unroll
            for (int p = 0; p < 4; p++) {
                const float x0 = xs[2 * p], x1 = xs[2 * p + 1];
                const __nv_bfloat16 h0 = __float2bfloat16(x0);
                const __nv_bfloat16 h1 = __float2bfloat16(x1);
                const __nv_bfloat16 l0 = __float2bfloat16(x0 - __bfloat162float(h0));
                const __nv_bfloat16 l1 = __float2bfloat16(x1 - __bfloat162float(h1));
                hp[p] = __nv_bfloat162(h0, h1);
                lp[p] = __nv_bfloat162(l0, l1);
            }
            *(uint4*)&As_hi[row * PADK + c8] = hv;
            *(uint4*)&As_lo[row * PADK + c8] = lv;
            *(uint4*)&Bs_hi[row * PADK + c8] = h ? pbh[1] : pbh[0];
            *(uint4*)&Bs_lo[row * PADK + c8] = h ? pbl[1] : pbl[0];
        }
        __syncthreads();

        // ---- prefetch next chunk ----
        if (kc + 1 < 16) {
            const int ko = (kc + 1) * 32;
            const float* a0 = keysA + (size_t)g0row * KD + ko + g0c;
            const float* a1 = keysA + (size_t)g1row * KD + ko + g1c;
            pa[0] = *(const float4*)(a0);     pa[1] = *(const float4*)(a0 + 4);
            pa[2] = *(const float4*)(a1);     pa[3] = *(const float4*)(a1 + 4);
            pbh[0] = *(const uint4*)(BtH + (size_t)g0row * KD + ko + g0c);
            pbh[1] = *(const uint4*)(BtH + (size_t)g1row * KD + ko + g1c);
            pbl[0] = *(const uint4*)(BtL + (size_t)g0row * KD + ko + g0c);
            pbl[1] = *(const uint4*)(BtL + (size_t)g1row * KD + ko + g1c);
        }

        // ---- MMAs over the chunk: 2 k-steps of k16 ----
        #pragma unroll
        for (int ks = 0; ks < 2; ks++) {
            const int kb = ks * 16;
            // A fragments
            uint32_t ah[4][4], al[4][4];
            const int arow = wm * 64 + (lid & 15);
            const int acol = kb + ((lid >> 4) << 3);
            #pragma unroll
            for (int mf = 0; mf < 4; mf++) {
                const uint32_t off = (uint32_t)(((arow + mf * 16) * PADK + acol) * 2);
                ldsm_x4(ah[mf], sAh + off);
                ldsm_x4(al[mf], sAl + off);
            }
            // B fragments (x4 covers two n8 frags)
            uint32_t bh[4][2], bl[4][2];
            const int brow = wn * 32 + ((lid >> 4) << 3) + (lid & 7);
            const int bcol = kb + (((lid >> 3) & 1) << 3);
            #pragma unroll
            for (int nf2 = 0; nf2 < 2; nf2++) {
                const uint32_t off = (uint32_t)(((brow + nf2 * 16) * PADK + bcol) * 2);
                uint32_t t[4];
                ldsm_x4(t, sBh + off);
                bh[2 * nf2][0] = t[0]; bh[2 * nf2][1] = t[1];
                bh[2 * nf2 + 1][0] = t[2]; bh[2 * nf2 + 1][1] = t[3];
                ldsm_x4(t, sBl + off);
                bl[2 * nf2][0] = t[0]; bl[2 * nf2][1] = t[1];
                bl[2 * nf2 + 1][0] = t[2]; bl[2 * nf2 + 1][1] = t[3];
            }
            // 3-term MMAs
            #pragma unroll
            for (int mf = 0; mf < 4; mf++)
                #pragma unroll
                for (int nf = 0; nf < 4; nf++) {
                    mma16816(acc[mf][nf], ah[mf], bh[nf]);
                    mma16816(acc[mf][nf], al[mf], bh[nf]);
                    mma16816(acc[mf][nf], ah[mf], bl[nf]);
                }
        }
        __syncthreads();
    }

    // ---- epilogue: e_partial[row] = sum over this block's 128 cols ----
    float qv[4][2], vv[4][2];
    #pragma unroll
    for (int nf = 0; nf < 4; nf++)
        #pragma unroll
        for (int j = 0; j < 2; j++) {
            const int col = nt * 128 + wn * 32 + nf * 8 + (lid & 3) * 2 + j;
            qv[nf][j] = g_qp[b * AD + col];
            vv[nf][j] = vvec[col];
        }

    float es[4][2];
    #pragma unroll
    for (int mf = 0; mf < 4; mf++)
        #pragma unroll
        for (int h = 0; h < 2; h++) {
            float s = 0.f;
            #pragma unroll
            for (int nf = 0; nf < 4; nf++) {
                s += tanh_fast(acc[mf][nf][2 * h + 0] + qv[nf][0]) * vv[nf][0];
                s += tanh_fast(acc[mf][nf][2 * h + 1] + qv[nf][1]) * vv[nf][1];
            }
            es[mf][h] = s;
        }
    // reduce across the 4 lanes of each quad (same row)
    #pragma unroll
    for (int off = 1; off <= 2; off <<= 1)
        #pragma unroll
        for (int mf = 0; mf < 4; mf++)
            #pragma unroll
            for (int h = 0; h < 2; h++)
                es[mf][h] += __shfl_xor_sync(0xffffffffu, es[mf][h], off);

    if ((lid & 3) == 0) {
        const int gq = lid >> 2;    // 0..7
        #pragma unroll
        for (int mf = 0; mf < 4; mf++)
            #pragma unroll
            for (int h = 0; h < 2; h++)
                e_red[wn][wm * 64 + mf * 16 + h * 8 + gq] = es[mf][h];
    }
    __syncthreads();
    if (tid < 128)
        g_epart[nt * MTOT + m0 + tid] =
            e_red[0][tid] + e_red[1][tid] + e_red[2][tid] + e_red[3][tid];
}

// ---------------------------------------------------------------------------
// Kernel 3: masked softmax over S per batch (sums 4 partials)
// ---------------------------------------------------------------------------
__global__ __launch_bounds__(1024)
void softmax_kernel(const int* __restrict__ mask, float* __restrict__ out) {
    const int b = blockIdx.x;
    const int t = threadIdx.x;
    const int lane = t & 31;
    const int wid  = t >> 5;
    __shared__ float sred[32];

    float sc[8];
    #pragma unroll
    for (int r = 0; r < 8; r++) {
        const int s = t + r * 1024;
        float e = g_epart[0 * MTOT + b * SS + s]
                + g_epart[1 * MTOT + b * SS + s]
                + g_epart[2 * MTOT + b * SS + s]
                + g_epart[3 * MTOT + b * SS + s];
        if (mask[b * SS + s] == 0) e = -FLT_MAX;
        sc[r] = e;
    }

    float m = sc[0];
    #pragma unroll
    for (int r = 1; r < 8; r++) m = fmaxf(m, sc[r]);
    #pragma unroll
    for (int off = 16; off > 0; off >>= 1)
        m = fmaxf(m, __shfl_xor_sync(0xffffffffu, m, off));
    if (lane == 0) sred[wid] = m;
    __syncthreads();
    if (t < 32) {
        float x = sred[t];
        #pragma unroll
        for (int off = 16; off > 0; off >>= 1)
            x = fmaxf(x, __shfl_xor_sync(0xffffffffu, x, off));
        if (t == 0) sred[0] = x;
    }
    __syncthreads();
    m = sred[0];
    __syncthreads();

    float ex[8];
    float sum = 0.f;
    #pragma unroll
    for (int r = 0; r < 8; r++) {
        ex[r] = expf(sc[r] - m);
        sum += ex[r];
    }
    #pragma unroll
    for (int off = 16; off > 0; off >>= 1)
        sum += __shfl_xor_sync(0xffffffffu, sum, off);
    if (lane == 0) sred[wid] = sum;
    __syncthreads();
    if (t < 32) {
        float x = sred[t];
        #pragma unroll
        for (int off = 16; off > 0; off >>= 1)
            x += __shfl_xor_sync(0xffffffffu, x, off);
        if (t == 0) sred[0] = x;
    }
    __syncthreads();
    const float inv = 1.f / sred[0];

    #pragma unroll
    for (int r = 0; r < 8; r++)
        out[BB * KD + b * SS + t + r * 1024] = ex[r] * inv;
}

// ---------------------------------------------------------------------------
// Kernel 4: context partials
// ---------------------------------------------------------------------------
__global__ __launch_bounds__(256)
void ctx_part_kernel(const float* __restrict__ keys,
                     const float* __restrict__ aout) {
    const int scn = blockIdx.x;
    const int b   = blockIdx.y;
    const int t   = threadIdx.x;
    __shared__ float as[128];
    if (t < 128) as[t] = aout[b * SS + scn * 128 + t];
    __syncthreads();

    const float* kb = keys + ((size_t)b * SS + (size_t)scn * 128) * KD;
    float s0 = 0.f, s1 = 0.f;
    for (int s = 0; s < 128; s++) {
        const float av = as[s];
        if (av != 0.f) {
            s0 += av * kb[(size_t)s * KD + t];
            s1 += av * kb[(size_t)s * KD + t + 256];
        }
    }
    g_cpart[(scn * BB + b) * KD + t]       = s0;
    g_cpart[(scn * BB + b) * KD + t + 256] = s1;
}

// ---------------------------------------------------------------------------
// Kernel 5: reduce context partials
// ---------------------------------------------------------------------------
__global__ __launch_bounds__(512)
void ctx_reduce_kernel(float* __restrict__ out) {
    const int b = blockIdx.x;
    const int t = threadIdx.x;
    float s = 0.f;
    #pragma unroll 8
    for (int scn = 0; scn < 64; scn++)
        s += g_cpart[(scn * BB + b) * KD + t];
    out[b * KD + t] = s;
}

// ---------------------------------------------------------------------------
extern "C" void kernel_launch(void* const* d_in, const int* in_sizes, int n_in,
                              void* d_out, int out_size) {
    const float* query = (const float*)d_in[0];
    const float* keys  = (const float*)d_in[1];
    const int*   mask  = (const int*)  d_in[2];
    const float* Wq    = (const float*)d_in[3];
    const float* Wk    = (const float*)d_in[4];
    const float* v     = (const float*)d_in[5];
    float* out = (float*)d_out;

    prep_wk_kernel<<<KD, AD>>>(Wk);
    qproj_kernel<<<BB, AD>>>(query, Wq);
    score_gemm_mma<<<dim3(4, 1024), 256>>>(keys, v);
    softmax_kernel<<<BB, 1024>>>(mask, out);
    ctx_part_kernel<<<dim3(64, BB), 256>>>(keys, out + BB * KD);
    ctx_reduce_kernel<<<BB, 512>>>(out);
}